// round 5
// baseline (speedup 1.0000x reference)
#include <cuda_runtime.h>
#include <cuda_bf16.h>
#include <cstdint>

#define NROWS 262144
#define CIN   256
#define MID   64
#define KOFF  9
#define EPS   1e-5f

// Pre-split bf16 tables for intermediates (device globals; no allocs allowed)
__device__ unsigned short g_h2hi[(size_t)NROWS * MID];
__device__ unsigned short g_h2lo[(size_t)NROWS * MID];
__device__ unsigned short g_h4hi[(size_t)NROWS * MID];
__device__ unsigned short g_h4lo[(size_t)NROWS * MID];
__device__ int g_mask_mode;

__device__ __forceinline__ uint32_t smem_to_u32(const void* p) {
    uint32_t a;
    asm("{ .reg .u64 t; cvta.to.shared.u64 t, %1; cvt.u32.u64 %0, t; }"
        : "=r"(a) : "l"(p));
    return a;
}

#define LDSM4(r, a)                                                            \
    asm volatile("ldmatrix.sync.aligned.m8n8.x4.shared.b16 {%0,%1,%2,%3}, [%4];" \
        : "=r"((r)[0]), "=r"((r)[1]), "=r"((r)[2]), "=r"((r)[3]) : "r"(a))

#define MMA_BF16(d, a, b)                                                      \
    asm volatile("mma.sync.aligned.m16n8k16.row.col.f32.bf16.bf16.f32 "        \
        "{%0,%1,%2,%3}, {%4,%5,%6,%7}, {%8,%9}, {%0,%1,%2,%3};"                \
        : "+f"((d)[0]), "+f"((d)[1]), "+f"((d)[2]), "+f"((d)[3])               \
        : "r"((a)[0]), "r"((a)[1]), "r"((a)[2]), "r"((a)[3]),                  \
          "r"((b)[0]), "r"((b)[1]))

__device__ __forceinline__ void split2(float v0, float v1, uint32_t& hi, uint32_t& lo) {
    __nv_bfloat16 h0 = __float2bfloat16(v0), h1 = __float2bfloat16(v1);
    __nv_bfloat16 l0 = __float2bfloat16(v0 - __bfloat162float(h0));
    __nv_bfloat16 l1 = __float2bfloat16(v1 - __bfloat162float(h1));
    hi = (uint32_t)__bfloat16_as_ushort(h0) | ((uint32_t)__bfloat16_as_ushort(h1) << 16);
    lo = (uint32_t)__bfloat16_as_ushort(l0) | ((uint32_t)__bfloat16_as_ushort(l1) << 16);
}
__device__ __forceinline__ void split1(float v, unsigned short& h, unsigned short& l) {
    __nv_bfloat16 hb = __float2bfloat16(v);
    __nv_bfloat16 lb = __float2bfloat16(v - __bfloat162float(hb));
    h = __bfloat16_as_ushort(hb); l = __bfloat16_as_ushort(lb);
}

// ---------------------------------------------------------------------------
// Mask dtype probe
// ---------------------------------------------------------------------------
__global__ void kDetect(const unsigned char* __restrict__ m) {
    if (threadIdx.x != 0 || blockIdx.x != 0) return;
    int saw3F_at1 = 0, saw3F = 0, sawNZ_nm4 = 0;
    for (int i = 0; i < 4096; i++) {
        unsigned char b = m[i];
        if (b == 0x3F) { saw3F = 1; if ((i & 3) == 1) saw3F_at1 = 1; }
        else if (b != 0 && (i & 3) != 0) sawNZ_nm4 = 1;
    }
    int mode;
    if (saw3F_at1)      mode = 3;
    else if (saw3F)     mode = 2;
    else if (sawNZ_nm4) mode = 1;
    else                mode = 0;
    g_mask_mode = mode;
}
__device__ __forceinline__ bool mask_on(const void* p, size_t i, int mode) {
    switch (mode) {
        case 1:  return ((const unsigned char*)p)[i] != 0;
        case 2:  return ((const float*)p)[i] != 0.0f;
        case 3:  return ((const unsigned short*)p)[i] != 0;
        default: return ((const int*)p)[i] != 0;
    }
}

// SMEM byte offsets. A tiles: [256 rows][72 bf16] (144B stride). B: [64 n][72 bf16].
#define ASTRIDE 144
#define AHI 0
#define ALO 36864
#define BHI 73728
#define BLO 82944
#define PAR 92160

// One 64-deep K chunk: warp computes 32x64 (two 16-row fragments), 3-MMA hi/lo.
__device__ __forceinline__ void gemm_chunk32(uint32_t sb, uint32_t aoff, uint32_t boff0,
                                             float acc[2][8][4]) {
    #pragma unroll
    for (int ks = 0; ks < 4; ks++) {
        uint32_t ah0[4], al0[4], ah1[4], al1[4];
        LDSM4(ah0, sb + AHI + aoff + ks * 32);
        LDSM4(ah1, sb + AHI + aoff + 16 * ASTRIDE + ks * 32);
        LDSM4(al0, sb + ALO + aoff + ks * 32);
        LDSM4(al1, sb + ALO + aoff + 16 * ASTRIDE + ks * 32);
        uint32_t bh[16], bl[16];
        #pragma unroll
        for (int p = 0; p < 4; p++) {
            LDSM4(bh + 4 * p, sb + BHI + boff0 + p * (16 * ASTRIDE) + ks * 32);
            LDSM4(bl + 4 * p, sb + BLO + boff0 + p * (16 * ASTRIDE) + ks * 32);
        }
        #pragma unroll
        for (int nt = 0; nt < 8; nt++) {
            const uint32_t* fh = bh + (nt >> 1) * 4 + (nt & 1) * 2;
            const uint32_t* fl = bl + (nt >> 1) * 4 + (nt & 1) * 2;
            MMA_BF16(acc[0][nt], ah0, fh);
            MMA_BF16(acc[1][nt], ah1, fh);
            MMA_BF16(acc[0][nt], ah0, fl);
            MMA_BF16(acc[1][nt], ah1, fl);
            MMA_BF16(acc[0][nt], al0, fh);
            MMA_BF16(acc[1][nt], al1, fh);
        }
    }
}

// Transpose a [64k x 64n] f32 weight chunk into split-bf16 B tiles [n][k].
__device__ __forceinline__ void build_B(char* smem, const float* __restrict__ wsrc,
                                        int ldw, int tid) {
    const int kr = tid >> 2, ns = (tid & 3) * 16;
    const float4* wr = reinterpret_cast<const float4*>(wsrc + (size_t)kr * ldw + ns);
    #pragma unroll
    for (int q = 0; q < 4; q++) {
        float4 v = wr[q];
        float e[4] = {v.x, v.y, v.z, v.w};
        #pragma unroll
        for (int j = 0; j < 4; j++) {
            int n = ns + q * 4 + j;
            unsigned short h, l; split1(e[j], h, l);
            *(unsigned short*)(smem + BHI + n * ASTRIDE + kr * 2) = h;
            *(unsigned short*)(smem + BLO + n * ASTRIDE + kr * 2) = l;
        }
    }
}

__device__ __forceinline__ uint32_t a_off(int wr0, int lane) {
    int row = wr0 + (lane & 7) + ((lane >> 3) & 1) * 8;
    return row * ASTRIDE + (lane >> 4) * 16;
}
__device__ __forceinline__ uint32_t b_off(int lane) {
    int n = (lane & 7) + (lane >> 4) * 8;
    return n * ASTRIDE + ((lane >> 3) & 1) * 16;
}

// ---------------------------------------------------------------------------
// Kernel A: h2 = relu(bn2( relu(bn1(x)) @ w1 + b1 )) -> g_h2hi/lo.  BM=256.
// ---------------------------------------------------------------------------
__global__ void __launch_bounds__(256)
kA(const float* __restrict__ x,
   const float* __restrict__ g1, const float* __restrict__ be1,
   const float* __restrict__ mu1, const float* __restrict__ va1,
   const float* __restrict__ w1, const float* __restrict__ b1,
   const float* __restrict__ g2, const float* __restrict__ be2,
   const float* __restrict__ mu2, const float* __restrict__ va2)
{
    extern __shared__ char smem[];
    const uint32_t sb = smem_to_u32(smem);
    float* s1 = (float*)(smem + PAR);
    float* t1 = s1 + 256; float* s2 = t1 + 256; float* u2 = s2 + 64;

    const int tid = threadIdx.x, lane = tid & 31, wid = tid >> 5;
    {
        float s = g1[tid] * rsqrtf(va1[tid] + EPS);
        s1[tid] = s; t1[tid] = be1[tid] - mu1[tid] * s;
    }
    if (tid < 64) {
        float s = g2[tid] * rsqrtf(va2[tid] + EPS);
        s2[tid] = s;
        u2[tid] = b1[tid] * s + (be2[tid] - mu2[tid] * s);
    }

    const int m0 = blockIdx.x * 256;
    const float* xrow = x + (size_t)(m0 + tid) * CIN;
    const uint32_t aoff = a_off(wid * 32, lane), boff = b_off(lane);
    float acc[2][8][4] = {};

    for (int ch = 0; ch < 4; ch++) {
        __syncthreads();
        // A tile: one full row per thread, bn1+relu+split
        {
            const float4* xr = reinterpret_cast<const float4*>(xrow + ch * 64);
            #pragma unroll
            for (int q = 0; q < 16; q++) {
                float4 v = xr[q];
                int cg = ch * 64 + q * 4;
                float a0 = fmaxf(v.x * s1[cg+0] + t1[cg+0], 0.0f);
                float a1 = fmaxf(v.y * s1[cg+1] + t1[cg+1], 0.0f);
                float a2 = fmaxf(v.z * s1[cg+2] + t1[cg+2], 0.0f);
                float a3 = fmaxf(v.w * s1[cg+3] + t1[cg+3], 0.0f);
                uint32_t h01, l01, h23, l23;
                split2(a0, a1, h01, l01); split2(a2, a3, h23, l23);
                int bo = tid * ASTRIDE + q * 8;
                *(uint32_t*)(smem + AHI + bo)     = h01;
                *(uint32_t*)(smem + AHI + bo + 4) = h23;
                *(uint32_t*)(smem + ALO + bo)     = l01;
                *(uint32_t*)(smem + ALO + bo + 4) = l23;
            }
        }
        build_B(smem, w1 + (size_t)(ch * 64) * MID, MID, tid);
        __syncthreads();
        gemm_chunk32(sb, aoff, boff, acc);
    }

    // Epilogue: bn2+relu, split, store (4 row groups: wid*32 + {0,8,16,24})
    const int rbase = m0 + wid * 32 + (lane >> 2);
    #pragma unroll
    for (int nt = 0; nt < 8; nt++) {
        int c0 = nt * 8 + (lane & 3) * 2;
        #pragma unroll
        for (int rr = 0; rr < 4; rr++) {
            int r = rbase + rr * 8;
            float* a = acc[rr >> 1][nt] + (rr & 1) * 2;
            float v0 = fmaxf(a[0] * s2[c0]   + u2[c0],   0.0f);
            float v1 = fmaxf(a[1] * s2[c0+1] + u2[c0+1], 0.0f);
            uint32_t h, l; split2(v0, v1, h, l);
            *(uint32_t*)(g_h2hi + (size_t)r * MID + c0) = h;
            *(uint32_t*)(g_h2lo + (size_t)r * MID + c0) = l;
        }
    }
}

// ---------------------------------------------------------------------------
// Kernel B: gather-GEMM over 9 offsets, h4 = relu(bn3(Σ gathered@w2 + b2))
// ---------------------------------------------------------------------------
__global__ void __launch_bounds__(256)
kB(const float* __restrict__ w2, const float* __restrict__ b2,
   const float* __restrict__ g3, const float* __restrict__ be3,
   const float* __restrict__ mu3, const float* __restrict__ va3,
   const int* __restrict__ nbr, const void* __restrict__ maskp)
{
    extern __shared__ char smem[];
    const uint32_t sb = smem_to_u32(smem);
    float* s3 = (float*)(smem + PAR);
    float* u3 = s3 + 64;

    const int tid = threadIdx.x, lane = tid & 31, wid = tid >> 5;
    if (tid < 64) {
        float s = g3[tid] * rsqrtf(va3[tid] + EPS);
        s3[tid] = s;
        u3[tid] = b2[tid] * s + (be3[tid] - mu3[tid] * s);
    }

    const int m0 = blockIdx.x * 256;
    const int mode = g_mask_mode;
    const uint32_t aoff = a_off(wid * 32, lane), boff = b_off(lane);
    float acc[2][8][4] = {};

    for (int k = 0; k < KOFF; k++) {
        __syncthreads();
        build_B(smem, w2 + (size_t)k * 4096, MID, tid);
        // gather one pre-split h2 row per thread
        {
            size_t e = (size_t)(m0 + tid) * KOFF + k;
            int idx = nbr[e];
            bool on = mask_on(maskp, e, mode);
            const uint4* hp = reinterpret_cast<const uint4*>(g_h2hi + (size_t)idx * MID);
            const uint4* lp = reinterpret_cast<const uint4*>(g_h2lo + (size_t)idx * MID);
            const uint4 z = make_uint4(0, 0, 0, 0);
            #pragma unroll
            for (int q = 0; q < 8; q++) {
                uint4 vh = on ? hp[q] : z;
                uint4 vl = on ? lp[q] : z;
                int bo = tid * ASTRIDE + q * 16;
                *(uint4*)(smem + AHI + bo) = vh;
                *(uint4*)(smem + ALO + bo) = vl;
            }
        }
        __syncthreads();
        gemm_chunk32(sb, aoff, boff, acc);
    }

    const int rbase = m0 + wid * 32 + (lane >> 2);
    #pragma unroll
    for (int nt = 0; nt < 8; nt++) {
        int c0 = nt * 8 + (lane & 3) * 2;
        #pragma unroll
        for (int rr = 0; rr < 4; rr++) {
            int r = rbase + rr * 8;
            float* a = acc[rr >> 1][nt] + (rr & 1) * 2;
            float v0 = fmaxf(a[0] * s3[c0]   + u3[c0],   0.0f);
            float v1 = fmaxf(a[1] * s3[c0+1] + u3[c0+1], 0.0f);
            uint32_t h, l; split2(v0, v1, h, l);
            *(uint32_t*)(g_h4hi + (size_t)r * MID + c0) = h;
            *(uint32_t*)(g_h4lo + (size_t)r * MID + c0) = l;
        }
    }
}

// ---------------------------------------------------------------------------
// Kernel C: out = h4 @ w3 + b3 + relu(bn1(x)).  BM=256, 4 col slices of 64.
// ---------------------------------------------------------------------------
__global__ void __launch_bounds__(256)
kC(const float* __restrict__ x,
   const float* __restrict__ g1, const float* __restrict__ be1,
   const float* __restrict__ mu1, const float* __restrict__ va1,
   const float* __restrict__ w3, const float* __restrict__ b3,
   float* __restrict__ out)
{
    extern __shared__ char smem[];
    const uint32_t sb = smem_to_u32(smem);
    float* s1c = (float*)(smem + PAR);
    float* t1c = s1c + 64; float* b3c = t1c + 64;

    const int tid = threadIdx.x, lane = tid & 31, wid = tid >> 5;
    const int m0 = blockIdx.y * 256;
    const int c0 = blockIdx.x * 64;

    if (tid < 64) {
        int c = c0 + tid;
        float s = g1[c] * rsqrtf(va1[c] + EPS);
        s1c[tid] = s; t1c[tid] = be1[c] - mu1[c] * s; b3c[tid] = b3[c];
    }
    // A tile: one pre-split h4 row per thread
    {
        const uint4* hp = reinterpret_cast<const uint4*>(g_h4hi + (size_t)(m0 + tid) * MID);
        const uint4* lp = reinterpret_cast<const uint4*>(g_h4lo + (size_t)(m0 + tid) * MID);
        #pragma unroll
        for (int q = 0; q < 8; q++) {
            int bo = tid * ASTRIDE + q * 16;
            *(uint4*)(smem + AHI + bo) = hp[q];
            *(uint4*)(smem + ALO + bo) = lp[q];
        }
    }
    build_B(smem, w3 + c0, CIN, tid);
    __syncthreads();

    const uint32_t aoff = a_off(wid * 32, lane), boff = b_off(lane);
    float acc[2][8][4] = {};
    gemm_chunk32(sb, aoff, boff, acc);

    // Epilogue: + b3 + shortcut, fp32 out
    const int rbase = m0 + wid * 32 + (lane >> 2);
    #pragma unroll
    for (int nt = 0; nt < 8; nt++) {
        int lc = nt * 8 + (lane & 3) * 2;
        int c = c0 + lc;
        #pragma unroll
        for (int rr = 0; rr < 4; rr++) {
            int r = rbase + rr * 8;
            const float* a = acc[rr >> 1][nt] + (rr & 1) * 2;
            float2 xv = *reinterpret_cast<const float2*>(x + (size_t)r * CIN + c);
            float o0 = a[0] + b3c[lc]   + fmaxf(xv.x * s1c[lc]   + t1c[lc],   0.0f);
            float o1 = a[1] + b3c[lc+1] + fmaxf(xv.y * s1c[lc+1] + t1c[lc+1], 0.0f);
            *reinterpret_cast<float2*>(out + (size_t)r * CIN + c) = make_float2(o0, o1);
        }
    }
}

// ---------------------------------------------------------------------------
extern "C" void kernel_launch(void* const* d_in, const int* in_sizes, int n_in,
                              void* d_out, int out_size)
{
    const float* x     = (const float*)d_in[0];
    const float* bn1_g = (const float*)d_in[1];
    const float* bn1_b = (const float*)d_in[2];
    const float* bn1_m = (const float*)d_in[3];
    const float* bn1_v = (const float*)d_in[4];
    const float* w1    = (const float*)d_in[5];
    const float* b1    = (const float*)d_in[6];
    const float* bn2_g = (const float*)d_in[7];
    const float* bn2_b = (const float*)d_in[8];
    const float* bn2_m = (const float*)d_in[9];
    const float* bn2_v = (const float*)d_in[10];
    const float* w2    = (const float*)d_in[11];
    const float* b2    = (const float*)d_in[12];
    const float* bn3_g = (const float*)d_in[13];
    const float* bn3_b = (const float*)d_in[14];
    const float* bn3_m = (const float*)d_in[15];
    const float* bn3_v = (const float*)d_in[16];
    const float* w3    = (const float*)d_in[17];
    const float* b3    = (const float*)d_in[18];
    const int*   nbr   = (const int*)d_in[19];
    const void*  msk   = (const void*)d_in[20];
    float* out = (float*)d_out;

    const int SMA = PAR + (256 + 256 + 64 + 64) * 4;
    const int SMB = PAR + (64 + 64) * 4;
    const int SMC = PAR + (64 + 64 + 64) * 4;
    cudaFuncSetAttribute(kA, cudaFuncAttributeMaxDynamicSharedMemorySize, SMA);
    cudaFuncSetAttribute(kB, cudaFuncAttributeMaxDynamicSharedMemorySize, SMB);
    cudaFuncSetAttribute(kC, cudaFuncAttributeMaxDynamicSharedMemorySize, SMC);

    kDetect<<<1, 1>>>((const unsigned char*)msk);
    kA<<<NROWS / 256, 256, SMA>>>(x, bn1_g, bn1_b, bn1_m, bn1_v, w1, b1,
                                  bn2_g, bn2_b, bn2_m, bn2_v);
    kB<<<NROWS / 256, 256, SMB>>>(w2, b2, bn3_g, bn3_b, bn3_m, bn3_v, nbr, msk);
    kC<<<dim3(4, NROWS / 256), 256, SMC>>>(x, bn1_g, bn1_b, bn1_m, bn1_v,
                                           w3, b3, out);
    (void)in_sizes; (void)n_in; (void)out_size;
}

// round 6
// speedup vs baseline: 1.1562x; 1.1562x over previous
#include <cuda_runtime.h>
#include <cuda_bf16.h>
#include <cstdint>

#define NROWS 262144
#define CIN   256
#define MID   64
#define KOFF  9
#define EPS   1e-5f

// Pre-split bf16 tables for h2 (device globals; no allocs allowed). h4 is fused away.
__device__ unsigned short g_h2hi[(size_t)NROWS * MID];
__device__ unsigned short g_h2lo[(size_t)NROWS * MID];
__device__ int g_mask_mode;

__device__ __forceinline__ uint32_t smem_to_u32(const void* p) {
    uint32_t a;
    asm("{ .reg .u64 t; cvta.to.shared.u64 t, %1; cvt.u32.u64 %0, t; }"
        : "=r"(a) : "l"(p));
    return a;
}

#define LDSM4(r, a)                                                            \
    asm volatile("ldmatrix.sync.aligned.m8n8.x4.shared.b16 {%0,%1,%2,%3}, [%4];" \
        : "=r"((r)[0]), "=r"((r)[1]), "=r"((r)[2]), "=r"((r)[3]) : "r"(a))

#define MMA_BF16(d, a, b)                                                      \
    asm volatile("mma.sync.aligned.m16n8k16.row.col.f32.bf16.bf16.f32 "        \
        "{%0,%1,%2,%3}, {%4,%5,%6,%7}, {%8,%9}, {%0,%1,%2,%3};"                \
        : "+f"((d)[0]), "+f"((d)[1]), "+f"((d)[2]), "+f"((d)[3])               \
        : "r"((a)[0]), "r"((a)[1]), "r"((a)[2]), "r"((a)[3]),                  \
          "r"((b)[0]), "r"((b)[1]))

#define CP_ASYNC16(dst, src, sz)                                               \
    asm volatile("cp.async.cg.shared.global [%0], [%1], 16, %2;"               \
                 :: "r"(dst), "l"(src), "r"(sz))
#define CP_COMMIT() asm volatile("cp.async.commit_group;" ::: "memory")
#define CP_WAIT1()  asm volatile("cp.async.wait_group 1;" ::: "memory")
#define CP_WAIT0()  asm volatile("cp.async.wait_group 0;" ::: "memory")

__device__ __forceinline__ void split2(float v0, float v1, uint32_t& hi, uint32_t& lo) {
    __nv_bfloat16 h0 = __float2bfloat16(v0), h1 = __float2bfloat16(v1);
    __nv_bfloat16 l0 = __float2bfloat16(v0 - __bfloat162float(h0));
    __nv_bfloat16 l1 = __float2bfloat16(v1 - __bfloat162float(h1));
    hi = (uint32_t)__bfloat16_as_ushort(h0) | ((uint32_t)__bfloat16_as_ushort(h1) << 16);
    lo = (uint32_t)__bfloat16_as_ushort(l0) | ((uint32_t)__bfloat16_as_ushort(l1) << 16);
}
__device__ __forceinline__ void split1(float v, unsigned short& h, unsigned short& l) {
    __nv_bfloat16 hb = __float2bfloat16(v);
    __nv_bfloat16 lb = __float2bfloat16(v - __bfloat162float(hb));
    h = __bfloat16_as_ushort(hb); l = __bfloat16_as_ushort(lb);
}

// ---------------------------------------------------------------------------
// Mask dtype probe
// ---------------------------------------------------------------------------
__global__ void kDetect(const unsigned char* __restrict__ m) {
    if (threadIdx.x != 0 || blockIdx.x != 0) return;
    int saw3F_at1 = 0, saw3F = 0, sawNZ_nm4 = 0;
    for (int i = 0; i < 4096; i++) {
        unsigned char b = m[i];
        if (b == 0x3F) { saw3F = 1; if ((i & 3) == 1) saw3F_at1 = 1; }
        else if (b != 0 && (i & 3) != 0) sawNZ_nm4 = 1;
    }
    int mode;
    if (saw3F_at1)      mode = 3;
    else if (saw3F)     mode = 2;
    else if (sawNZ_nm4) mode = 1;
    else                mode = 0;
    g_mask_mode = mode;
}
__device__ __forceinline__ bool mask_on(const void* p, size_t i, int mode) {
    switch (mode) {
        case 1:  return ((const unsigned char*)p)[i] != 0;
        case 2:  return ((const float*)p)[i] != 0.0f;
        case 3:  return ((const unsigned short*)p)[i] != 0;
        default: return ((const int*)p)[i] != 0;
    }
}

#define ASTRIDE 144

// Warp tile 16x64, 3-MMA hi/lo scheme over one 64-deep K chunk (R4-proven).
__device__ __forceinline__ void gemm_chunk16(uint32_t sb, uint32_t ahi, uint32_t alo,
                                             uint32_t bhi, uint32_t blo,
                                             uint32_t aoff, uint32_t boff,
                                             float acc[8][4]) {
    #pragma unroll
    for (int ks = 0; ks < 4; ks++) {
        uint32_t ah[4], al[4];
        LDSM4(ah, sb + ahi + aoff + ks * 32);
        LDSM4(al, sb + alo + aoff + ks * 32);
        uint32_t bh[16], bl[16];
        #pragma unroll
        for (int p = 0; p < 4; p++) {
            LDSM4(bh + 4 * p, sb + bhi + boff + p * (16 * ASTRIDE) + ks * 32);
            LDSM4(bl + 4 * p, sb + blo + boff + p * (16 * ASTRIDE) + ks * 32);
        }
        #pragma unroll
        for (int nt = 0; nt < 8; nt++) {
            const uint32_t* fh = bh + (nt >> 1) * 4 + (nt & 1) * 2;
            const uint32_t* fl = bl + (nt >> 1) * 4 + (nt & 1) * 2;
            MMA_BF16(acc[nt], ah, fh);
            MMA_BF16(acc[nt], ah, fl);
            MMA_BF16(acc[nt], al, fh);
        }
    }
}

// Transpose a [64k x 64n] f32 weight chunk into split-bf16 B tiles [n][k].
__device__ __forceinline__ void build_B(char* smem, uint32_t bhi, uint32_t blo,
                                        const float* __restrict__ wsrc,
                                        int ldw, int tid) {
    const int kr = tid >> 2, ns = (tid & 3) * 16;
    const float4* wr = reinterpret_cast<const float4*>(wsrc + (size_t)kr * ldw + ns);
    #pragma unroll
    for (int q = 0; q < 4; q++) {
        float4 v = wr[q];
        float e[4] = {v.x, v.y, v.z, v.w};
        #pragma unroll
        for (int j = 0; j < 4; j++) {
            int n = ns + q * 4 + j;
            unsigned short h, l; split1(e[j], h, l);
            *(unsigned short*)(smem + bhi + n * ASTRIDE + kr * 2) = h;
            *(unsigned short*)(smem + blo + n * ASTRIDE + kr * 2) = l;
        }
    }
}

__device__ __forceinline__ uint32_t a_off(int wr0, int lane) {
    int row = wr0 + (lane & 7) + ((lane >> 3) & 1) * 8;
    return row * ASTRIDE + (lane >> 4) * 16;
}
__device__ __forceinline__ uint32_t b_off(int lane) {
    int n = (lane & 7) + (lane >> 4) * 8;
    return n * ASTRIDE + ((lane >> 3) & 1) * 16;
}

// ---------------------------------------------------------------------------
// Kernel A (R4-identical): h2 = relu(bn2( relu(bn1(x)) @ w1 + b1 )). BM=128.
// ---------------------------------------------------------------------------
#define A_AHI 0
#define A_ALO 18432
#define A_BHI 36864
#define A_BLO 46080
#define A_PAR 55296

__global__ void __launch_bounds__(256)
kA(const float* __restrict__ x,
   const float* __restrict__ g1, const float* __restrict__ be1,
   const float* __restrict__ mu1, const float* __restrict__ va1,
   const float* __restrict__ w1, const float* __restrict__ b1,
   const float* __restrict__ g2, const float* __restrict__ be2,
   const float* __restrict__ mu2, const float* __restrict__ va2)
{
    extern __shared__ char smem[];
    const uint32_t sb = smem_to_u32(smem);
    float* s1 = (float*)(smem + A_PAR);
    float* t1 = s1 + 256; float* s2 = t1 + 256; float* u2 = s2 + 64;

    const int tid = threadIdx.x, lane = tid & 31, wid = tid >> 5;
    {
        float s = g1[tid] * rsqrtf(va1[tid] + EPS);
        s1[tid] = s; t1[tid] = be1[tid] - mu1[tid] * s;
    }
    if (tid < 64) {
        float s = g2[tid] * rsqrtf(va2[tid] + EPS);
        s2[tid] = s;
        u2[tid] = b1[tid] * s + (be2[tid] - mu2[tid] * s);
    }

    const int m0 = blockIdx.x * 128;
    const int row = tid >> 1, half = tid & 1;
    const float* xrow = x + (size_t)(m0 + row) * CIN + half * 32;
    const uint32_t aoff = a_off(wid * 16, lane), boff = b_off(lane);
    float acc[8][4] = {};

    for (int ch = 0; ch < 4; ch++) {
        __syncthreads();
        {
            const float4* xr = reinterpret_cast<const float4*>(xrow + ch * 64);
            #pragma unroll
            for (int q = 0; q < 8; q++) {
                float4 v = xr[q];
                int cg = ch * 64 + half * 32 + q * 4;
                float a0 = fmaxf(v.x * s1[cg+0] + t1[cg+0], 0.0f);
                float a1 = fmaxf(v.y * s1[cg+1] + t1[cg+1], 0.0f);
                float a2 = fmaxf(v.z * s1[cg+2] + t1[cg+2], 0.0f);
                float a3 = fmaxf(v.w * s1[cg+3] + t1[cg+3], 0.0f);
                uint32_t h01, l01, h23, l23;
                split2(a0, a1, h01, l01); split2(a2, a3, h23, l23);
                int bo = row * ASTRIDE + half * 64 + q * 8;
                *(uint32_t*)(smem + A_AHI + bo)     = h01;
                *(uint32_t*)(smem + A_AHI + bo + 4) = h23;
                *(uint32_t*)(smem + A_ALO + bo)     = l01;
                *(uint32_t*)(smem + A_ALO + bo + 4) = l23;
            }
        }
        build_B(smem, A_BHI, A_BLO, w1 + (size_t)(ch * 64) * MID, MID, tid);
        __syncthreads();
        gemm_chunk16(sb, A_AHI, A_ALO, A_BHI, A_BLO, aoff, boff, acc);
    }

    const int r0 = m0 + wid * 16 + (lane >> 2);
    #pragma unroll
    for (int nt = 0; nt < 8; nt++) {
        int c0 = nt * 8 + (lane & 3) * 2;
        float v00 = fmaxf(acc[nt][0] * s2[c0]   + u2[c0],   0.0f);
        float v01 = fmaxf(acc[nt][1] * s2[c0+1] + u2[c0+1], 0.0f);
        float v10 = fmaxf(acc[nt][2] * s2[c0]   + u2[c0],   0.0f);
        float v11 = fmaxf(acc[nt][3] * s2[c0+1] + u2[c0+1], 0.0f);
        uint32_t h0, l0, h1, l1;
        split2(v00, v01, h0, l0); split2(v10, v11, h1, l1);
        *(uint32_t*)(g_h2hi + (size_t)r0 * MID + c0)     = h0;
        *(uint32_t*)(g_h2lo + (size_t)r0 * MID + c0)     = l0;
        *(uint32_t*)(g_h2hi + (size_t)(r0+8) * MID + c0) = h1;
        *(uint32_t*)(g_h2lo + (size_t)(r0+8) * MID + c0) = l1;
    }
}

// ---------------------------------------------------------------------------
// Fused kBC: phase 1 = gather-GEMM over 9 offsets (cp.async double-buffered),
// phase 2 = h4 (in smem) @ w3 + b3 + shortcut, 4 col slices of 64.
// ---------------------------------------------------------------------------
#define F_A0HI 0
#define F_A0LO 18432
#define F_A1HI 36864
#define F_A1LO 55296
#define F_BHI  73728
#define F_BLO  82944
#define F_PAR  92160

__global__ void __launch_bounds__(256)
kBC(const float* __restrict__ x,
    const float* __restrict__ g1, const float* __restrict__ be1,
    const float* __restrict__ mu1, const float* __restrict__ va1,
    const float* __restrict__ w2, const float* __restrict__ b2,
    const float* __restrict__ g3, const float* __restrict__ be3,
    const float* __restrict__ mu3, const float* __restrict__ va3,
    const float* __restrict__ w3, const float* __restrict__ b3,
    const int* __restrict__ nbr, const void* __restrict__ maskp,
    float* __restrict__ out)
{
    extern __shared__ char smem[];
    const uint32_t sb = smem_to_u32(smem);
    float* s3  = (float*)(smem + F_PAR);        // [64]
    float* u3  = s3 + 64;                       // [64]
    float* s1a = u3 + 64;                       // [256]
    float* t1a = s1a + 256;                     // [256]
    float* b3a = t1a + 256;                     // [256]

    const int tid = threadIdx.x, lane = tid & 31, wid = tid >> 5;
    if (tid < 64) {
        float s = g3[tid] * rsqrtf(va3[tid] + EPS);
        s3[tid] = s;
        u3[tid] = b2[tid] * s + (be3[tid] - mu3[tid] * s);
    }
    {
        float s = g1[tid] * rsqrtf(va1[tid] + EPS);
        s1a[tid] = s; t1a[tid] = be1[tid] - mu1[tid] * s; b3a[tid] = b3[tid];
    }

    const int m0 = blockIdx.x * 128;
    const int row = tid >> 1, half = tid & 1;
    const int mode = g_mask_mode;
    const uint32_t aoff = a_off(wid * 16, lane), boff = b_off(lane);

    // Gather issue: pre-split h2 row -> A buffer `buf` via cp.async (zero-fill if masked)
    auto issue_gather = [&](int kk, int buf) {
        size_t e = (size_t)(m0 + row) * KOFF + kk;
        int idx = nbr[e];
        uint32_t sz = mask_on(maskp, e, mode) ? 16u : 0u;
        const char* hp = (const char*)(g_h2hi + (size_t)idx * MID + half * 32);
        const char* lp = (const char*)(g_h2lo + (size_t)idx * MID + half * 32);
        uint32_t dh = sb + (buf ? F_A1HI : F_A0HI) + row * ASTRIDE + half * 64;
        uint32_t dl = sb + (buf ? F_A1LO : F_A0LO) + row * ASTRIDE + half * 64;
        #pragma unroll
        for (int q = 0; q < 4; q++) {
            CP_ASYNC16(dh + q * 16, hp + q * 16, sz);
            CP_ASYNC16(dl + q * 16, lp + q * 16, sz);
        }
        CP_COMMIT();
    };

    float acc[8][4] = {};
    issue_gather(0, 0);                 // prologue

    // ---------------- Phase 1: 9 gather chunks ----------------
    for (int k = 0; k < KOFF; k++) {
        __syncthreads();                // prev gemm done (Bbuf + A[(k+1)&1] free)
        build_B(smem, F_BHI, F_BLO, w2 + (size_t)k * 4096, MID, tid);
        if (k < KOFF - 1) { issue_gather(k + 1, (k + 1) & 1); CP_WAIT1(); }
        else              { CP_WAIT0(); }
        __syncthreads();                // A[k&1] + B visible to all
        gemm_chunk16(sb, (k & 1) ? F_A1HI : F_A0HI, (k & 1) ? F_A1LO : F_A0LO,
                     F_BHI, F_BLO, aoff, boff, acc);
    }

    // ---------------- Transition: h4 = relu(bn3(acc)) -> A buffer 0 ----------------
    __syncthreads();
    {
        const int rl = wid * 16 + (lane >> 2);
        #pragma unroll
        for (int nt = 0; nt < 8; nt++) {
            int c0 = nt * 8 + (lane & 3) * 2;
            #pragma unroll
            for (int rr = 0; rr < 2; rr++) {
                int r = rl + rr * 8;
                const float* a = acc[nt] + rr * 2;
                float v0 = fmaxf(a[0] * s3[c0]   + u3[c0],   0.0f);
                float v1 = fmaxf(a[1] * s3[c0+1] + u3[c0+1], 0.0f);
                uint32_t h, l; split2(v0, v1, h, l);
                int bo = r * ASTRIDE + c0 * 2;
                *(uint32_t*)(smem + F_A0HI + bo) = h;
                *(uint32_t*)(smem + F_A0LO + bo) = l;
            }
        }
    }

    // ---------------- Phase 2: out = h4 @ w3 + b3 + relu(bn1(x)), 4 slices ----------------
    const int rbase = m0 + wid * 16 + (lane >> 2);
    for (int s = 0; s < 4; s++) {
        __syncthreads();                // h4 tile ready / prev gemm done with Bbuf
        build_B(smem, F_BHI, F_BLO, w3 + s * 64, CIN, tid);
        __syncthreads();
        float acc2[8][4] = {};
        gemm_chunk16(sb, F_A0HI, F_A0LO, F_BHI, F_BLO, aoff, boff, acc2);

        #pragma unroll
        for (int nt = 0; nt < 8; nt++) {
            int lc = nt * 8 + (lane & 3) * 2;
            int c = s * 64 + lc;
            #pragma unroll
            for (int rr = 0; rr < 2; rr++) {
                int r = rbase + rr * 8;
                const float* a = acc2[nt] + rr * 2;
                float2 xv = *reinterpret_cast<const float2*>(x + (size_t)r * CIN + c);
                float o0 = a[0] + b3a[c]   + fmaxf(xv.x * s1a[c]   + t1a[c],   0.0f);
                float o1 = a[1] + b3a[c+1] + fmaxf(xv.y * s1a[c+1] + t1a[c+1], 0.0f);
                *reinterpret_cast<float2*>(out + (size_t)r * CIN + c) = make_float2(o0, o1);
            }
        }
    }
}

// ---------------------------------------------------------------------------
extern "C" void kernel_launch(void* const* d_in, const int* in_sizes, int n_in,
                              void* d_out, int out_size)
{
    const float* x     = (const float*)d_in[0];
    const float* bn1_g = (const float*)d_in[1];
    const float* bn1_b = (const float*)d_in[2];
    const float* bn1_m = (const float*)d_in[3];
    const float* bn1_v = (const float*)d_in[4];
    const float* w1    = (const float*)d_in[5];
    const float* b1    = (const float*)d_in[6];
    const float* bn2_g = (const float*)d_in[7];
    const float* bn2_b = (const float*)d_in[8];
    const float* bn2_m = (const float*)d_in[9];
    const float* bn2_v = (const float*)d_in[10];
    const float* w2    = (const float*)d_in[11];
    const float* b2    = (const float*)d_in[12];
    const float* bn3_g = (const float*)d_in[13];
    const float* bn3_b = (const float*)d_in[14];
    const float* bn3_m = (const float*)d_in[15];
    const float* bn3_v = (const float*)d_in[16];
    const float* w3    = (const float*)d_in[17];
    const float* b3    = (const float*)d_in[18];
    const int*   nbr   = (const int*)d_in[19];
    const void*  msk   = (const void*)d_in[20];
    float* out = (float*)d_out;

    const int SMA  = A_PAR + (256 + 256 + 64 + 64) * 4;
    const int SMBC = F_PAR + (64 + 64 + 256 + 256 + 256) * 4;
    cudaFuncSetAttribute(kA,  cudaFuncAttributeMaxDynamicSharedMemorySize, SMA);
    cudaFuncSetAttribute(kBC, cudaFuncAttributeMaxDynamicSharedMemorySize, SMBC);

    kDetect<<<1, 1>>>((const unsigned char*)msk);
    kA<<<NROWS / 128, 256, SMA>>>(x, bn1_g, bn1_b, bn1_m, bn1_v, w1, b1,
                                  bn2_g, bn2_b, bn2_m, bn2_v);
    kBC<<<NROWS / 128, 256, SMBC>>>(x, bn1_g, bn1_b, bn1_m, bn1_v,
                                    w2, b2, bn3_g, bn3_b, bn3_m, bn3_v,
                                    w3, b3, nbr, msk, out);
    (void)in_sizes; (void)n_in; (void)out_size;
}

// round 7
// speedup vs baseline: 1.2526x; 1.0834x over previous
#include <cuda_runtime.h>
#include <cuda_bf16.h>
#include <cstdint>

#define NROWS 262144
#define CIN   256
#define MID   64
#define KOFF  9
#define EPS   1e-5f

// Pre-split bf16 tables for h2 (device globals; no allocs allowed). h4 is fused away.
__device__ unsigned short g_h2hi[(size_t)NROWS * MID];
__device__ unsigned short g_h2lo[(size_t)NROWS * MID];
__device__ int g_mask_mode;

__device__ __forceinline__ uint32_t smem_to_u32(const void* p) {
    uint32_t a;
    asm("{ .reg .u64 t; cvta.to.shared.u64 t, %1; cvt.u32.u64 %0, t; }"
        : "=r"(a) : "l"(p));
    return a;
}

#define LDSM4(r, a)                                                            \
    asm volatile("ldmatrix.sync.aligned.m8n8.x4.shared.b16 {%0,%1,%2,%3}, [%4];" \
        : "=r"((r)[0]), "=r"((r)[1]), "=r"((r)[2]), "=r"((r)[3]) : "r"(a))

#define MMA_BF16(d, a, b)                                                      \
    asm volatile("mma.sync.aligned.m16n8k16.row.col.f32.bf16.bf16.f32 "        \
        "{%0,%1,%2,%3}, {%4,%5,%6,%7}, {%8,%9}, {%0,%1,%2,%3};"                \
        : "+f"((d)[0]), "+f"((d)[1]), "+f"((d)[2]), "+f"((d)[3])               \
        : "r"((a)[0]), "r"((a)[1]), "r"((a)[2]), "r"((a)[3]),                  \
          "r"((b)[0]), "r"((b)[1]))

#define CP_ASYNC16(dst, src, sz)                                               \
    asm volatile("cp.async.cg.shared.global [%0], [%1], 16, %2;"               \
                 :: "r"(dst), "l"(src), "r"(sz))
#define CP_COMMIT() asm volatile("cp.async.commit_group;" ::: "memory")
#define CP_WAIT1()  asm volatile("cp.async.wait_group 1;" ::: "memory")
#define CP_WAIT0()  asm volatile("cp.async.wait_group 0;" ::: "memory")

__device__ __forceinline__ void split2(float v0, float v1, uint32_t& hi, uint32_t& lo) {
    __nv_bfloat16 h0 = __float2bfloat16(v0), h1 = __float2bfloat16(v1);
    __nv_bfloat16 l0 = __float2bfloat16(v0 - __bfloat162float(h0));
    __nv_bfloat16 l1 = __float2bfloat16(v1 - __bfloat162float(h1));
    hi = (uint32_t)__bfloat16_as_ushort(h0) | ((uint32_t)__bfloat16_as_ushort(h1) << 16);
    lo = (uint32_t)__bfloat16_as_ushort(l0) | ((uint32_t)__bfloat16_as_ushort(l1) << 16);
}
__device__ __forceinline__ void split1(float v, unsigned short& h, unsigned short& l) {
    __nv_bfloat16 hb = __float2bfloat16(v);
    __nv_bfloat16 lb = __float2bfloat16(v - __bfloat162float(hb));
    h = __bfloat16_as_ushort(hb); l = __bfloat16_as_ushort(lb);
}

// ---------------------------------------------------------------------------
// Mask dtype probe — parallel (256 threads x 16 bytes), one DRAM round-trip.
// ---------------------------------------------------------------------------
__global__ void kDetect(const unsigned char* __restrict__ m) {
    __shared__ int flags[3];    // [0]=saw3F_at1  [1]=saw3F  [2]=sawNZ_nm4
    const int tid = threadIdx.x;
    if (tid < 3) flags[tid] = 0;
    __syncthreads();
    int f0 = 0, f1 = 0, f2 = 0;
    #pragma unroll
    for (int q = 0; q < 16; q++) {
        int i = tid * 16 + q;
        unsigned char b = m[i];
        if (b == 0x3F) { f1 = 1; if ((i & 3) == 1) f0 = 1; }
        else if (b != 0 && (i & 3) != 0) f2 = 1;
    }
    if (f0) atomicOr(&flags[0], 1);
    if (f1) atomicOr(&flags[1], 1);
    if (f2) atomicOr(&flags[2], 1);
    __syncthreads();
    if (tid == 0) {
        int mode;
        if (flags[0])      mode = 3;   // bf16
        else if (flags[1]) mode = 2;   // float32
        else if (flags[2]) mode = 1;   // uint8/bool
        else               mode = 0;   // int32
        g_mask_mode = mode;
    }
}
__device__ __forceinline__ bool mask_on(const void* p, size_t i, int mode) {
    switch (mode) {
        case 1:  return ((const unsigned char*)p)[i] != 0;
        case 2:  return ((const float*)p)[i] != 0.0f;
        case 3:  return ((const unsigned short*)p)[i] != 0;
        default: return ((const int*)p)[i] != 0;
    }
}

#define ASTRIDE 144

// Warp tile 16x64, 3-MMA hi/lo scheme over one 64-deep K chunk (R4-proven).
__device__ __forceinline__ void gemm_chunk16(uint32_t sb, uint32_t ahi, uint32_t alo,
                                             uint32_t bhi, uint32_t blo,
                                             uint32_t aoff, uint32_t boff,
                                             float acc[8][4]) {
    #pragma unroll
    for (int ks = 0; ks < 4; ks++) {
        uint32_t ah[4], al[4];
        LDSM4(ah, sb + ahi + aoff + ks * 32);
        LDSM4(al, sb + alo + aoff + ks * 32);
        uint32_t bh[16], bl[16];
        #pragma unroll
        for (int p = 0; p < 4; p++) {
            LDSM4(bh + 4 * p, sb + bhi + boff + p * (16 * ASTRIDE) + ks * 32);
            LDSM4(bl + 4 * p, sb + blo + boff + p * (16 * ASTRIDE) + ks * 32);
        }
        #pragma unroll
        for (int nt = 0; nt < 8; nt++) {
            const uint32_t* fh = bh + (nt >> 1) * 4 + (nt & 1) * 2;
            const uint32_t* fl = bl + (nt >> 1) * 4 + (nt & 1) * 2;
            MMA_BF16(acc[nt], ah, fh);
            MMA_BF16(acc[nt], ah, fl);
            MMA_BF16(acc[nt], al, fh);
        }
    }
}

// Transpose a [64k x 64n] f32 weight chunk into split-bf16 B tiles [n][k].
__device__ __forceinline__ void build_B(char* smem, uint32_t bhi, uint32_t blo,
                                        const float* __restrict__ wsrc,
                                        int ldw, int tid) {
    const int kr = tid >> 2, ns = (tid & 3) * 16;
    const float4* wr = reinterpret_cast<const float4*>(wsrc + (size_t)kr * ldw + ns);
    #pragma unroll
    for (int q = 0; q < 4; q++) {
        float4 v = wr[q];
        float e[4] = {v.x, v.y, v.z, v.w};
        #pragma unroll
        for (int j = 0; j < 4; j++) {
            int n = ns + q * 4 + j;
            unsigned short h, l; split1(e[j], h, l);
            *(unsigned short*)(smem + bhi + n * ASTRIDE + kr * 2) = h;
            *(unsigned short*)(smem + blo + n * ASTRIDE + kr * 2) = l;
        }
    }
}

__device__ __forceinline__ uint32_t a_off(int wr0, int lane) {
    int row = wr0 + (lane & 7) + ((lane >> 3) & 1) * 8;
    return row * ASTRIDE + (lane >> 4) * 16;
}
__device__ __forceinline__ uint32_t b_off(int lane) {
    int n = (lane & 7) + (lane >> 4) * 8;
    return n * ASTRIDE + ((lane >> 3) & 1) * 16;
}

// ---------------------------------------------------------------------------
// Kernel A: h2 = relu(bn2( relu(bn1(x)) @ w1 + b1 )). BM=128.
// x-tile loads prefetched into registers one chunk ahead (hidden behind MMAs).
// ---------------------------------------------------------------------------
#define A_AHI 0
#define A_ALO 18432
#define A_BHI 36864
#define A_BLO 46080
#define A_PAR 55296

__global__ void __launch_bounds__(256)
kA(const float* __restrict__ x,
   const float* __restrict__ g1, const float* __restrict__ be1,
   const float* __restrict__ mu1, const float* __restrict__ va1,
   const float* __restrict__ w1, const float* __restrict__ b1,
   const float* __restrict__ g2, const float* __restrict__ be2,
   const float* __restrict__ mu2, const float* __restrict__ va2)
{
    extern __shared__ char smem[];
    const uint32_t sb = smem_to_u32(smem);
    float* s1 = (float*)(smem + A_PAR);
    float* t1 = s1 + 256; float* s2 = t1 + 256; float* u2 = s2 + 64;

    const int tid = threadIdx.x, lane = tid & 31, wid = tid >> 5;
    {
        float s = g1[tid] * rsqrtf(va1[tid] + EPS);
        s1[tid] = s; t1[tid] = be1[tid] - mu1[tid] * s;
    }
    if (tid < 64) {
        float s = g2[tid] * rsqrtf(va2[tid] + EPS);
        s2[tid] = s;
        u2[tid] = b1[tid] * s + (be2[tid] - mu2[tid] * s);
    }

    const int m0 = blockIdx.x * 128;
    const int row = tid >> 1, half = tid & 1;
    const float4* xr4 = reinterpret_cast<const float4*>(
        x + (size_t)(m0 + row) * CIN + half * 32);
    const uint32_t aoff = a_off(wid * 16, lane), boff = b_off(lane);
    float acc[8][4] = {};

    float4 xbuf[8];
    #pragma unroll
    for (int q = 0; q < 8; q++) xbuf[q] = xr4[q];   // prologue: chunk 0

    for (int ch = 0; ch < 4; ch++) {
        __syncthreads();
        // A tile from prefetched registers: bn1+relu+split
        #pragma unroll
        for (int q = 0; q < 8; q++) {
            float4 v = xbuf[q];
            int cg = ch * 64 + half * 32 + q * 4;
            float a0 = fmaxf(v.x * s1[cg+0] + t1[cg+0], 0.0f);
            float a1 = fmaxf(v.y * s1[cg+1] + t1[cg+1], 0.0f);
            float a2 = fmaxf(v.z * s1[cg+2] + t1[cg+2], 0.0f);
            float a3 = fmaxf(v.w * s1[cg+3] + t1[cg+3], 0.0f);
            uint32_t h01, l01, h23, l23;
            split2(a0, a1, h01, l01); split2(a2, a3, h23, l23);
            int bo = row * ASTRIDE + half * 64 + q * 8;
            *(uint32_t*)(smem + A_AHI + bo)     = h01;
            *(uint32_t*)(smem + A_AHI + bo + 4) = h23;
            *(uint32_t*)(smem + A_ALO + bo)     = l01;
            *(uint32_t*)(smem + A_ALO + bo + 4) = l23;
        }
        build_B(smem, A_BHI, A_BLO, w1 + (size_t)(ch * 64) * MID, MID, tid);
        __syncthreads();
        if (ch < 3) {
            #pragma unroll
            for (int q = 0; q < 8; q++) xbuf[q] = xr4[(ch + 1) * 16 + q];
        }
        gemm_chunk16(sb, A_AHI, A_ALO, A_BHI, A_BLO, aoff, boff, acc);
    }

    const int r0 = m0 + wid * 16 + (lane >> 2);
    #pragma unroll
    for (int nt = 0; nt < 8; nt++) {
        int c0 = nt * 8 + (lane & 3) * 2;
        float v00 = fmaxf(acc[nt][0] * s2[c0]   + u2[c0],   0.0f);
        float v01 = fmaxf(acc[nt][1] * s2[c0+1] + u2[c0+1], 0.0f);
        float v10 = fmaxf(acc[nt][2] * s2[c0]   + u2[c0],   0.0f);
        float v11 = fmaxf(acc[nt][3] * s2[c0+1] + u2[c0+1], 0.0f);
        uint32_t h0, l0, h1, l1;
        split2(v00, v01, h0, l0); split2(v10, v11, h1, l1);
        *(uint32_t*)(g_h2hi + (size_t)r0 * MID + c0)     = h0;
        *(uint32_t*)(g_h2lo + (size_t)r0 * MID + c0)     = l0;
        *(uint32_t*)(g_h2hi + (size_t)(r0+8) * MID + c0) = h1;
        *(uint32_t*)(g_h2lo + (size_t)(r0+8) * MID + c0) = l1;
    }
}

// ---------------------------------------------------------------------------
// Fused kBC (R6-identical): phase 1 = gather-GEMM over 9 offsets (cp.async
// double-buffered), phase 2 = h4 (in smem) @ w3 + b3 + shortcut, 4 col slices.
// ---------------------------------------------------------------------------
#define F_A0HI 0
#define F_A0LO 18432
#define F_A1HI 36864
#define F_A1LO 55296
#define F_BHI  73728
#define F_BLO  82944
#define F_PAR  92160

__global__ void __launch_bounds__(256)
kBC(const float* __restrict__ x,
    const float* __restrict__ g1, const float* __restrict__ be1,
    const float* __restrict__ mu1, const float* __restrict__ va1,
    const float* __restrict__ w2, const float* __restrict__ b2,
    const float* __restrict__ g3, const float* __restrict__ be3,
    const float* __restrict__ mu3, const float* __restrict__ va3,
    const float* __restrict__ w3, const float* __restrict__ b3,
    const int* __restrict__ nbr, const void* __restrict__ maskp,
    float* __restrict__ out)
{
    extern __shared__ char smem[];
    const uint32_t sb = smem_to_u32(smem);
    float* s3  = (float*)(smem + F_PAR);        // [64]
    float* u3  = s3 + 64;                       // [64]
    float* s1a = u3 + 64;                       // [256]
    float* t1a = s1a + 256;                     // [256]
    float* b3a = t1a + 256;                     // [256]

    const int tid = threadIdx.x, lane = tid & 31, wid = tid >> 5;
    if (tid < 64) {
        float s = g3[tid] * rsqrtf(va3[tid] + EPS);
        s3[tid] = s;
        u3[tid] = b2[tid] * s + (be3[tid] - mu3[tid] * s);
    }
    {
        float s = g1[tid] * rsqrtf(va1[tid] + EPS);
        s1a[tid] = s; t1a[tid] = be1[tid] - mu1[tid] * s; b3a[tid] = b3[tid];
    }

    const int m0 = blockIdx.x * 128;
    const int row = tid >> 1, half = tid & 1;
    const int mode = g_mask_mode;
    const uint32_t aoff = a_off(wid * 16, lane), boff = b_off(lane);

    auto issue_gather = [&](int kk, int buf) {
        size_t e = (size_t)(m0 + row) * KOFF + kk;
        int idx = nbr[e];
        uint32_t sz = mask_on(maskp, e, mode) ? 16u : 0u;
        const char* hp = (const char*)(g_h2hi + (size_t)idx * MID + half * 32);
        const char* lp = (const char*)(g_h2lo + (size_t)idx * MID + half * 32);
        uint32_t dh = sb + (buf ? F_A1HI : F_A0HI) + row * ASTRIDE + half * 64;
        uint32_t dl = sb + (buf ? F_A1LO : F_A0LO) + row * ASTRIDE + half * 64;
        #pragma unroll
        for (int q = 0; q < 4; q++) {
            CP_ASYNC16(dh + q * 16, hp + q * 16, sz);
            CP_ASYNC16(dl + q * 16, lp + q * 16, sz);
        }
        CP_COMMIT();
    };

    float acc[8][4] = {};
    issue_gather(0, 0);                 // prologue

    // ---------------- Phase 1: 9 gather chunks ----------------
    for (int k = 0; k < KOFF; k++) {
        __syncthreads();                // prev gemm done (Bbuf + A[(k+1)&1] free)
        build_B(smem, F_BHI, F_BLO, w2 + (size_t)k * 4096, MID, tid);
        if (k < KOFF - 1) { issue_gather(k + 1, (k + 1) & 1); CP_WAIT1(); }
        else              { CP_WAIT0(); }
        __syncthreads();                // A[k&1] + B visible to all
        gemm_chunk16(sb, (k & 1) ? F_A1HI : F_A0HI, (k & 1) ? F_A1LO : F_A0LO,
                     F_BHI, F_BLO, aoff, boff, acc);
    }

    // ---------------- Transition: h4 = relu(bn3(acc)) -> A buffer 0 ----------------
    __syncthreads();
    {
        const int rl = wid * 16 + (lane >> 2);
        #pragma unroll
        for (int nt = 0; nt < 8; nt++) {
            int c0 = nt * 8 + (lane & 3) * 2;
            #pragma unroll
            for (int rr = 0; rr < 2; rr++) {
                int r = rl + rr * 8;
                const float* a = acc[nt] + rr * 2;
                float v0 = fmaxf(a[0] * s3[c0]   + u3[c0],   0.0f);
                float v1 = fmaxf(a[1] * s3[c0+1] + u3[c0+1], 0.0f);
                uint32_t h, l; split2(v0, v1, h, l);
                int bo = r * ASTRIDE + c0 * 2;
                *(uint32_t*)(smem + F_A0HI + bo) = h;
                *(uint32_t*)(smem + F_A0LO + bo) = l;
            }
        }
    }

    // ---------------- Phase 2: out = h4 @ w3 + b3 + relu(bn1(x)), 4 slices ----------------
    const int rbase = m0 + wid * 16 + (lane >> 2);
    for (int s = 0; s < 4; s++) {
        __syncthreads();                // h4 tile ready / prev gemm done with Bbuf
        build_B(smem, F_BHI, F_BLO, w3 + s * 64, CIN, tid);
        __syncthreads();
        float acc2[8][4] = {};
        gemm_chunk16(sb, F_A0HI, F_A0LO, F_BHI, F_BLO, aoff, boff, acc2);

        #pragma unroll
        for (int nt = 0; nt < 8; nt++) {
            int lc = nt * 8 + (lane & 3) * 2;
            int c = s * 64 + lc;
            #pragma unroll
            for (int rr = 0; rr < 2; rr++) {
                int r = rbase + rr * 8;
                const float* a = acc2[nt] + rr * 2;
                float2 xv = *reinterpret_cast<const float2*>(x + (size_t)r * CIN + c);
                float o0 = a[0] + b3a[c]   + fmaxf(xv.x * s1a[c]   + t1a[c],   0.0f);
                float o1 = a[1] + b3a[c+1] + fmaxf(xv.y * s1a[c+1] + t1a[c+1], 0.0f);
                *reinterpret_cast<float2*>(out + (size_t)r * CIN + c) = make_float2(o0, o1);
            }
        }
    }
}

// ---------------------------------------------------------------------------
extern "C" void kernel_launch(void* const* d_in, const int* in_sizes, int n_in,
                              void* d_out, int out_size)
{
    const float* x     = (const float*)d_in[0];
    const float* bn1_g = (const float*)d_in[1];
    const float* bn1_b = (const float*)d_in[2];
    const float* bn1_m = (const float*)d_in[3];
    const float* bn1_v = (const float*)d_in[4];
    const float* w1    = (const float*)d_in[5];
    const float* b1    = (const float*)d_in[6];
    const float* bn2_g = (const float*)d_in[7];
    const float* bn2_b = (const float*)d_in[8];
    const float* bn2_m = (const float*)d_in[9];
    const float* bn2_v = (const float*)d_in[10];
    const float* w2    = (const float*)d_in[11];
    const float* b2    = (const float*)d_in[12];
    const float* bn3_g = (const float*)d_in[13];
    const float* bn3_b = (const float*)d_in[14];
    const float* bn3_m = (const float*)d_in[15];
    const float* bn3_v = (const float*)d_in[16];
    const float* w3    = (const float*)d_in[17];
    const float* b3    = (const float*)d_in[18];
    const int*   nbr   = (const int*)d_in[19];
    const void*  msk   = (const void*)d_in[20];
    float* out = (float*)d_out;

    const int SMA  = A_PAR + (256 + 256 + 64 + 64) * 4;
    const int SMBC = F_PAR + (64 + 64 + 256 + 256 + 256) * 4;
    cudaFuncSetAttribute(kA,  cudaFuncAttributeMaxDynamicSharedMemorySize, SMA);
    cudaFuncSetAttribute(kBC, cudaFuncAttributeMaxDynamicSharedMemorySize, SMBC);

    kDetect<<<1, 256>>>((const unsigned char*)msk);
    kA<<<NROWS / 128, 256, SMA>>>(x, bn1_g, bn1_b, bn1_m, bn1_v, w1, b1,
                                  bn2_g, bn2_b, bn2_m, bn2_v);
    kBC<<<NROWS / 128, 256, SMBC>>>(x, bn1_g, bn1_b, bn1_m, bn1_v,
                                    w2, b2, bn3_g, bn3_b, bn3_m, bn3_v,
                                    w3, b3, nbr, msk, out);
    (void)in_sizes; (void)n_in; (void)out_size;
}